// round 10
// baseline (speedup 1.0000x reference)
#include <cuda_runtime.h>
#include <cstdint>
#include <math.h>

#define NB 128

// ---------------- scratch (device globals: no allocation allowed) -------------
__device__ uint32_t g_a1[NB*32*32*4];    // 128 ch @32x32 (packed bits)
__device__ uint32_t g_a2[NB*16*16*4];
__device__ uint32_t g_a3[NB*16*16*8];
__device__ uint32_t g_a4[NB*8*8*8];
__device__ uint32_t g_a5[NB*8*8*16];
__device__ uint32_t g_a6[NB*4*4*16];

// int8 sign weights, layout [tap][oc][cin]
__device__ int8_t g_w8_2[9*128*128];
__device__ int8_t g_w8_3[9*256*128];
__device__ int8_t g_w8_4[9*256*256];
__device__ int8_t g_w8_5[9*512*256];
__device__ int8_t g_w8_6[9*512*512];
__device__ uint32_t g_w7p[16*16*10];     // conv7 packed bits (quad layout)

// ---------------- weight prep: float -> int8 sign, [tap][oc][cin] -------------
__global__ void prepW8(const float* __restrict__ w, int8_t* __restrict__ w8,
                       int CIN, int COUT) {
    int i = blockIdx.x * blockDim.x + threadIdx.x;
    int n = 9 * COUT * CIN;
    if (i >= n) return;
    int cin = i % CIN;
    int oc  = (i / CIN) % COUT;
    int tap = i / (CIN * COUT);
    float v = w[(oc * CIN + cin) * 9 + tap];
    w8[i] = (v > 0.f) ? (int8_t)1 : (int8_t)-1;
}

// ---------------- conv7 weight pack (bit, quad layout) -------------------------
__global__ void pack7(const float* __restrict__ w7, uint32_t* __restrict__ wp) {
    int gw = blockIdx.x * 8 + (threadIdx.x >> 5);
    int lane = threadIdx.x & 31;
    if (gw >= 2560) return;                    // 10 oc * 16 kk * 16 wi
    int oc = gw / 256;
    int r  = gw % 256;
    int kk = r / 16, wi = r % 16;
    float v = w7[(oc * 512 + wi * 32 + lane) * 16 + kk];
    unsigned word = __ballot_sync(0xffffffffu, v > 0.f);
    if (lane == 0)
        wp[((kk * 4 + (wi >> 2)) * 10 + oc) * 4 + (wi & 3)] = word;
}

// ---------------- layer 1: fp32 conv (3->128) + BN-sign -> bits ---------------
// Accumulation order matches XLA:CPU EigenConv2D. DO NOT CHANGE per-chain order.
__global__ void layer1(const float* __restrict__ x, const float* __restrict__ w1,
                       const float* __restrict__ s1, const float* __restrict__ t1) {
    __shared__ float ws[3456];
    __shared__ float xs[3 * 3 * 34];
    int b = blockIdx.x >> 5;
    int y = blockIdx.x & 31;
    int tid = threadIdx.x;

    for (int i = tid; i < 3456; i += 128) ws[i] = w1[i];
    for (int i = tid; i < 306; i += 128) {
        int c = i / 102;
        int r = (i % 102) / 34;
        int col = i % 34;
        int yin = y + r - 1, xin = col - 1;
        float v = 0.f;
        if (yin >= 0 && yin < 32 && xin >= 0 && xin < 32)
            v = x[((b * 3 + c) * 32 + yin) * 32 + xin];
        xs[i] = v;
    }
    __syncthreads();

    int oc = tid;
    float wsgn[27];
#pragma unroll
    for (int k = 0; k < 27; k++) {
        float wv = ws[oc * 27 + k];
        wsgn[k] = (wv > 0.f) ? 1.f : ((wv < 0.f) ? -1.f : 0.f);
    }
    float sv = s1[oc], tv = t1[oc];
    int lane = tid & 31, wid = tid >> 5;

    for (int x8 = 0; x8 < 32; x8 += 8) {
        float acc[8];
#pragma unroll
        for (int u = 0; u < 8; u++) {
            int xo = x8 + u;
            float a = 0.f;
#pragma unroll
            for (int ky = 0; ky < 3; ky++)
#pragma unroll
                for (int kx = 0; kx < 3; kx++)
#pragma unroll
                    for (int c = 0; c < 3; c++)
                        a = __fmaf_rn(xs[c * 102 + ky * 34 + xo + kx],
                                      wsgn[c * 9 + ky * 3 + kx], a);
            acc[u] = a;
        }
#pragma unroll
        for (int u = 0; u < 8; u++) {
            float v = __fadd_rn(__fmul_rn(acc[u], sv), tv);
            unsigned word = __ballot_sync(0xffffffffu, v > 0.f);
            if (lane == 0)
                g_a1[((b * 32 + y) * 32 + x8 + u) * 4 + wid] = word;
        }
    }
}

// ---------------- int8 tensor-core conv layer ---------------------------------
__device__ __forceinline__ void mma_s8(int* c, uint32_t a0, uint32_t a1,
                                       uint32_t a2, uint32_t a3,
                                       uint32_t b0, uint32_t b1) {
    asm volatile(
        "mma.sync.aligned.m16n8k32.row.col.s32.s8.s8.s32 "
        "{%0,%1,%2,%3}, {%4,%5,%6,%7}, {%8,%9}, {%0,%1,%2,%3};"
        : "+r"(c[0]), "+r"(c[1]), "+r"(c[2]), "+r"(c[3])
        : "r"(a0), "r"(a1), "r"(a2), "r"(a3), "r"(b0), "r"(b1));
}

// CTA: 64 output pixels (STRIP rows x W) x NC output channels; 8 warps.
// smem: int8 slab [(STRIP+2)][(W+2)][CIN] (zero halo = exact padding),
//       B chunk [NC][64] (k-contiguous per oc), BN s/t arrays.
// dot products exact integers (s32) == reference fp32 integer sums.
template <int CIN, int H, int W, int STRIP, int POOL, int NC, int NWN, int COUT>
__global__ __launch_bounds__(256) void mmaconv(const uint32_t* __restrict__ in,
                                               uint32_t* __restrict__ out,
                                               const int8_t* __restrict__ w8,
                                               const float* __restrict__ s,
                                               const float* __restrict__ t) {
    constexpr int CINW = CIN / 32;
    constexpr int SLABW = W + 2;
    constexpr int SLABR = STRIP + 2;
    constexpr int NWM = 8 / NWN;
    constexpr int MT = 64 / (16 * NWM);
    constexpr int ASZ = SLABR * SLABW * CIN;
    constexpr int BSZ = NC * 64;
    constexpr int NCW = NC / 32;
    constexpr int OCWT = COUT / 32;
    static_assert(STRIP * W == 64, "strip");

    extern __shared__ char smem[];
    char* A = smem;
    char* B = smem + ASZ;
    float* sS = (float*)(smem + ASZ + BSZ);
    float* sT = sS + NC;

    int tid = threadIdx.x;
    int lane = tid & 31, wid = tid >> 5;
    int SPI = H / STRIP;
    int b  = blockIdx.x / SPI;
    int st = blockIdx.x % SPI;
    int y0 = st * STRIP;
    int ocg = blockIdx.y;
    int nGlob = ocg * NC;

    // stage BN params
    for (int i = tid; i < NC; i += 256) { sS[i] = s[nGlob + i]; sT[i] = t[nGlob + i]; }
    // zero slab
    uint4 z = make_uint4(0u, 0u, 0u, 0u);
    for (int i = tid; i < ASZ / 16; i += 256) reinterpret_cast<uint4*>(A)[i] = z;
    __syncthreads();
    // expand packed bits -> int8 +-1 into slab interior (global-valid rows only)
    for (int i = tid; i < SLABR * W * CINW; i += 256) {
        int cw = i % CINW;
        int xx = (i / CINW) % W;
        int ly = i / (CINW * W);
        int ygl = y0 - 1 + ly;
        if (ygl >= 0 && ygl < H) {
            uint32_t word = in[((b * H + ygl) * W + xx) * CINW + cw];
            uint32_t* dst = reinterpret_cast<uint32_t*>(
                A + (ly * SLABW + (xx + 1)) * CIN + cw * 32);
#pragma unroll
            for (int j = 0; j < 8; j++) {
                uint32_t nib = (word >> (4 * j)) & 0xFu;
                uint32_t sp = (nib * 0x00204081u) & 0x01010101u;
                dst[j] = ~(sp * 0xFEu);      // bit->+1, else -1
            }
        }
    }
    __syncthreads();

    // per-lane pixel base offsets (slab bytes) for fragment rows
    int wm = wid / NWN, wn = wid % NWN;
    int mWarpBase = wm * (MT * 16);
    int nWarpBase = wn * 64;
    int rowOff[MT][2];
#pragma unroll
    for (int mt = 0; mt < MT; mt++)
#pragma unroll
        for (int h = 0; h < 2; h++) {
            int p = mWarpBase + mt * 16 + (lane >> 2) + 8 * h;
            int ly = p / W, xx = p % W;
            rowOff[mt][h] = (ly * SLABW + xx) * CIN;
        }

    int acc[MT][8][4];
#pragma unroll
    for (int mt = 0; mt < MT; mt++)
#pragma unroll
        for (int nt = 0; nt < 8; nt++)
#pragma unroll
            for (int c = 0; c < 4; c++) acc[mt][nt][c] = 0;

    for (int tap = 0; tap < 9; tap++) {
        int ky = tap / 3, kx = tap % 3;
        int tapOff = (ky * SLABW + kx) * CIN;
        for (int cin0 = 0; cin0 < CIN; cin0 += 64) {
            __syncthreads();   // protect previous B chunk
            for (int i = tid; i < NC * 4; i += 256) {
                int ocl = i >> 2, part = i & 3;
                reinterpret_cast<uint4*>(B + ocl * 64)[part] =
                    *reinterpret_cast<const uint4*>(
                        w8 + ((size_t)tap * COUT + nGlob + ocl) * CIN + cin0 + part * 16);
            }
            __syncthreads();
#pragma unroll
            for (int ks = 0; ks < 2; ks++) {
                uint32_t a[MT][4];
#pragma unroll
                for (int mt = 0; mt < MT; mt++) {
                    const char* p0 = A + rowOff[mt][0] + tapOff + cin0 + ks * 32 + (lane & 3) * 4;
                    const char* p1 = A + rowOff[mt][1] + tapOff + cin0 + ks * 32 + (lane & 3) * 4;
                    a[mt][0] = *reinterpret_cast<const uint32_t*>(p0);
                    a[mt][1] = *reinterpret_cast<const uint32_t*>(p1);
                    a[mt][2] = *reinterpret_cast<const uint32_t*>(p0 + 16);
                    a[mt][3] = *reinterpret_cast<const uint32_t*>(p1 + 16);
                }
#pragma unroll
                for (int nt = 0; nt < 8; nt++) {
                    const char* pb = B + (nWarpBase + nt * 8 + (lane >> 2)) * 64
                                     + ks * 32 + (lane & 3) * 4;
                    uint32_t b0 = *reinterpret_cast<const uint32_t*>(pb);
                    uint32_t b1 = *reinterpret_cast<const uint32_t*>(pb + 16);
#pragma unroll
                    for (int mt = 0; mt < MT; mt++)
                        mma_s8(acc[mt][nt], a[mt][0], a[mt][1], a[mt][2], a[mt][3], b0, b1);
                }
            }
        }
    }

    // epilogue: threshold bytes into smem (reuse B region), then ballot-pack
    __syncthreads();
    char* E = B;
#pragma unroll
    for (int mt = 0; mt < MT; mt++)
#pragma unroll
        for (int nt = 0; nt < 8; nt++)
#pragma unroll
            for (int c = 0; c < 4; c++) {
                int p = mWarpBase + mt * 16 + (lane >> 2) + ((c >= 2) ? 8 : 0);
                int ocl = nWarpBase + nt * 8 + (lane & 3) * 2 + (c & 1);
                float v = __fadd_rn(__fmul_rn((float)acc[mt][nt][c], sS[ocl]), sT[ocl]);
                E[p * NC + ocl] = (v > 0.f) ? 1 : 0;
            }
    __syncthreads();

    if constexpr (POOL) {
        constexpr int TASKS = (STRIP / 2) * (W / 2) * NCW;
        for (int task = wid; task < TASKS; task += 8) {
            int ow = task % NCW;
            int q = task / NCW;
            int qx = q % (W / 2), qy = q / (W / 2);
            int ocl = ow * 32 + lane;
            int p00 = (2 * qy) * W + 2 * qx;
            int bsum = E[p00 * NC + ocl] | E[(p00 + 1) * NC + ocl]
                     | E[(p00 + W) * NC + ocl] | E[(p00 + W + 1) * NC + ocl];
            unsigned word = __ballot_sync(0xffffffffu, bsum != 0);
            if (lane == 0)
                out[((b * (H / 2) + (y0 / 2 + qy)) * (W / 2) + qx) * OCWT
                    + ocg * NCW + ow] = word;
        }
    } else {
        constexpr int TASKS = 64 * NCW;
        for (int task = wid; task < TASKS; task += 8) {
            int ow = task % NCW;
            int q = task / NCW;
            int xx = q % W, ly = q / W;
            int ocl = ow * 32 + lane;
            unsigned word = __ballot_sync(0xffffffffu, E[q * NC + ocl] != 0);
            if (lane == 0)
                out[((b * H + (y0 + ly)) * W + xx) * OCWT + ocg * NCW + ow] = word;
        }
    }
}

// ---------------- layer 7: 4x4 VALID conv (512->10) + BN + log_softmax --------
__global__ void conv7(const float* __restrict__ s, const float* __restrict__ t,
                      float* __restrict__ outp) {
    int b = blockIdx.x;
    int wid = threadIdx.x >> 5, lane = threadIdx.x & 31;
    __shared__ float logits[10];

    int msum = 0;
    for (int i = lane; i < 256; i += 32) {
        int kk = i >> 4, wi = i & 15;
        uint32_t wv = g_w7p[((kk * 4 + (wi >> 2)) * 10 + wid) * 4 + (wi & 3)];
        msum += __popc(g_a6[b * 256 + i] ^ wv);
    }
#pragma unroll
    for (int off = 16; off; off >>= 1)
        msum += __shfl_down_sync(0xffffffffu, msum, off);
    if (lane == 0) {
        int dot = 8192 - 2 * msum;
        logits[wid] = __fadd_rn(__fmul_rn((float)dot, s[wid]), t[wid]);
    }
    __syncthreads();
    if (threadIdx.x == 0) {
        float mx = logits[0];
        for (int i = 1; i < 10; i++) mx = fmaxf(mx, logits[i]);
        float ssum = 0.f;
        for (int i = 0; i < 10; i++) ssum += expf(logits[i] - mx);
        float lse = mx + logf(ssum);
        for (int i = 0; i < 10; i++) outp[b * 10 + i] = logits[i] - lse;
    }
}

// ---------------- launcher ----------------------------------------------------
extern "C" void kernel_launch(void* const* d_in, const int* in_sizes, int n_in,
                              void* d_out, int out_size) {
    const float* x  = (const float*)d_in[0];
    const float* w1 = (const float*)d_in[1];
    const float* w2 = (const float*)d_in[2];
    const float* w3 = (const float*)d_in[3];
    const float* w4 = (const float*)d_in[4];
    const float* w5 = (const float*)d_in[5];
    const float* w6 = (const float*)d_in[6];
    const float* w7 = (const float*)d_in[7];
    const float* bns[7];
    const float* bnt[7];
    for (int i = 0; i < 7; i++) {
        bns[i] = (const float*)d_in[8 + 2 * i];
        bnt[i] = (const float*)d_in[9 + 2 * i];
    }
    float* out = (float*)d_out;

    void *pa1, *pa2, *pa3, *pa4, *pa5, *pa6;
    void *pw2, *pw3, *pw4, *pw5, *pw6, *pw7;
    cudaGetSymbolAddress(&pa1, g_a1);
    cudaGetSymbolAddress(&pa2, g_a2);
    cudaGetSymbolAddress(&pa3, g_a3);
    cudaGetSymbolAddress(&pa4, g_a4);
    cudaGetSymbolAddress(&pa5, g_a5);
    cudaGetSymbolAddress(&pa6, g_a6);
    cudaGetSymbolAddress(&pw2, g_w8_2);
    cudaGetSymbolAddress(&pw3, g_w8_3);
    cudaGetSymbolAddress(&pw4, g_w8_4);
    cudaGetSymbolAddress(&pw5, g_w8_5);
    cudaGetSymbolAddress(&pw6, g_w8_6);
    cudaGetSymbolAddress(&pw7, g_w7p);

    // weight prep
    prepW8<<<(9*128*128 + 255) / 256, 256>>>(w2, (int8_t*)pw2, 128, 128);
    prepW8<<<(9*256*128 + 255) / 256, 256>>>(w3, (int8_t*)pw3, 128, 256);
    prepW8<<<(9*256*256 + 255) / 256, 256>>>(w4, (int8_t*)pw4, 256, 256);
    prepW8<<<(9*512*256 + 255) / 256, 256>>>(w5, (int8_t*)pw5, 256, 512);
    prepW8<<<(9*512*512 + 255) / 256, 256>>>(w6, (int8_t*)pw6, 512, 512);
    pack7<<<320, 256>>>(w7, (uint32_t*)pw7);

    layer1<<<NB * 32, 128>>>(x, w1, bns[0], bnt[0]);

    // mma conv layers: <CIN,H,W,STRIP,POOL,NC,NWN,COUT>, smem = slab + B + 2*NC floats
    {   // L2: 128ch 32x32 -> pool -> 128ch 16x16
        constexpr int SM = 4*34*128 + 128*64 + 128*8;   // 26624
        auto k = mmaconv<128, 32, 32, 2, 1, 128, 2, 128>;
        cudaFuncSetAttribute(k, cudaFuncAttributeMaxDynamicSharedMemorySize, SM);
        k<<<dim3(NB * 16, 1), 256, SM>>>((uint32_t*)pa1, (uint32_t*)pa2,
                                         (int8_t*)pw2, bns[1], bnt[1]);
    }
    {   // L3: 128 -> 256 @16x16
        constexpr int SM = 6*18*128 + 256*64 + 256*8;   // 32256
        auto k = mmaconv<128, 16, 16, 4, 0, 256, 4, 256>;
        cudaFuncSetAttribute(k, cudaFuncAttributeMaxDynamicSharedMemorySize, SM);
        k<<<dim3(NB * 4, 1), 256, SM>>>((uint32_t*)pa2, (uint32_t*)pa3,
                                        (int8_t*)pw3, bns[2], bnt[2]);
    }
    {   // L4: 256 -> 256 @16x16 -> pool -> 8x8
        constexpr int SM = 6*18*256 + 256*64 + 256*8;   // 46080
        auto k = mmaconv<256, 16, 16, 4, 1, 256, 4, 256>;
        cudaFuncSetAttribute(k, cudaFuncAttributeMaxDynamicSharedMemorySize, SM);
        k<<<dim3(NB * 4, 1), 256, SM>>>((uint32_t*)pa3, (uint32_t*)pa4,
                                        (int8_t*)pw4, bns[3], bnt[3]);
    }
    {   // L5: 256 -> 512 @8x8 (2 oc groups)
        constexpr int SM = 10*10*256 + 256*64 + 256*8;  // 44032
        auto k = mmaconv<256, 8, 8, 8, 0, 256, 4, 512>;
        cudaFuncSetAttribute(k, cudaFuncAttributeMaxDynamicSharedMemorySize, SM);
        k<<<dim3(NB, 2), 256, SM>>>((uint32_t*)pa4, (uint32_t*)pa5,
                                    (int8_t*)pw5, bns[4], bnt[4]);
    }
    {   // L6: 512 -> 512 @8x8 -> pool -> 4x4 (2 oc groups)
        constexpr int SM = 10*10*512 + 256*64 + 256*8;  // 69632
        auto k = mmaconv<512, 8, 8, 8, 1, 256, 4, 512>;
        cudaFuncSetAttribute(k, cudaFuncAttributeMaxDynamicSharedMemorySize, SM);
        k<<<dim3(NB, 2), 256, SM>>>((uint32_t*)pa5, (uint32_t*)pa6,
                                    (int8_t*)pw6, bns[5], bnt[5]);
    }

    conv7<<<NB, 320>>>(bns[6], bnt[6], out);
}

// round 12
// speedup vs baseline: 2.8109x; 2.8109x over previous
#include <cuda_runtime.h>
#include <cstdint>
#include <math.h>

#define NB 128

// ---------------- scratch (device globals: no allocation allowed) -------------
__device__ uint32_t g_a1[NB*32*32*4];    // 128 ch @32x32
__device__ uint32_t g_a2[NB*16*16*4];    // 128 ch @16x16
__device__ uint32_t g_a3[NB*16*16*8];    // 256 ch @16x16
__device__ uint32_t g_a4[NB*8*8*8];      // 256 ch @8x8
__device__ uint32_t g_a5[NB*8*8*16];     // 512 ch @8x8
__device__ uint32_t g_a6[NB*4*4*16];     // 512 ch @4x4

// Packed weight sign bits, quad layout: [kk][cinword/4][oc][4] (uint4-loadable)
__device__ uint32_t g_w2p[9*4*128];
__device__ uint32_t g_w3p[9*4*256];
__device__ uint32_t g_w4p[9*8*256];
__device__ uint32_t g_w5p[9*8*512];
__device__ uint32_t g_w6p[9*16*512];
__device__ uint32_t g_w7p[16*16*10];

// ---------------- CSA helpers --------------------------------------------------
__device__ __forceinline__ void csa(uint32_t& s, uint32_t& c,
                                    uint32_t a, uint32_t b, uint32_t d) {
    s = a ^ b ^ d;                       // 1 LOP3
    c = (a & b) | (a & d) | (b & d);     // 1 LOP3 (majority)
}

// Sum of popcounts of 12 words via 7 CSAs -> 5 popcs (exact integer).
__device__ __forceinline__ int popc12(const uint32_t* p) {
    uint32_t s0,c0,s1,c1,s2,c2,s3,c3,t0,d0,u0,e0,u1,e1;
    csa(s0,c0,p[0],p[1],p[2]);
    csa(s1,c1,p[3],p[4],p[5]);
    csa(s2,c2,p[6],p[7],p[8]);
    csa(s3,c3,p[9],p[10],p[11]);
    csa(t0,d0,s0,s1,s2);
    csa(u0,e0,c0,c1,c2);
    csa(u1,e1,c3,d0,u0);
    return __popc(t0) + __popc(s3) + 2*__popc(u1) + 4*(__popc(e0) + __popc(e1));
}

// ---------------- merged weight packer ----------------------------------------
__global__ void packAll(const float* w2, const float* w3, const float* w4,
                        const float* w5, const float* w6, const float* w7,
                        uint32_t* p2, uint32_t* p3, uint32_t* p4,
                        uint32_t* p5, uint32_t* p6, uint32_t* p7) {
    __shared__ float sw[8192];           // up to 512*16 floats (w7) = 32KB
    int bid = blockIdx.x;
    const float* w; uint32_t* wp; int CIN, KK, COUT, oc;
    if (bid < 128)       { w = w2; wp = p2; CIN = 128; KK = 9;  COUT = 128; oc = bid; }
    else if (bid < 384)  { w = w3; wp = p3; CIN = 128; KK = 9;  COUT = 256; oc = bid - 128; }
    else if (bid < 640)  { w = w4; wp = p4; CIN = 256; KK = 9;  COUT = 256; oc = bid - 384; }
    else if (bid < 1152) { w = w5; wp = p5; CIN = 256; KK = 9;  COUT = 512; oc = bid - 640; }
    else if (bid < 1664) { w = w6; wp = p6; CIN = 512; KK = 9;  COUT = 512; oc = bid - 1152; }
    else                 { w = w7; wp = p7; CIN = 512; KK = 16; COUT = 10;  oc = bid - 1664; }

    int n = CIN * KK;
    int tid = threadIdx.x;
    for (int i = tid; i < n; i += 256) sw[i] = w[oc * n + i];
    __syncthreads();
    int CINW = CIN >> 5;
    int W = KK * CINW;
    int wid = tid >> 5, lane = tid & 31;
    for (int widx = wid; widx < W; widx += 8) {
        int kk = widx / CINW;            // CINW is a power of 2
        int wi = widx - kk * CINW;
        float v = sw[(wi * 32 + lane) * KK + kk];
        unsigned word = __ballot_sync(0xffffffffu, v > 0.f);
        if (lane == 0)
            wp[((kk * (CINW >> 2) + (wi >> 2)) * COUT + oc) * 4 + (wi & 3)] = word;
    }
}

// ---------------- layer 1: fp32 conv (3->128) + BN-sign -> bits ---------------
// Accumulation order matches XLA:CPU EigenConv2D (NHWC RowMajor): sequential
// fma, C fastest, kx middle, ky outermost. DO NOT CHANGE per-chain order.
__global__ void layer1(const float* __restrict__ x, const float* __restrict__ w1,
                       const float* __restrict__ s1, const float* __restrict__ t1) {
    __shared__ float ws[3456];        // w1 raw (128*27)
    __shared__ float xs[3 * 3 * 34];  // [c][ky][xin+1], zero-padded columns/rows
    int b = blockIdx.x >> 5;
    int y = blockIdx.x & 31;
    int tid = threadIdx.x;

    for (int i = tid; i < 3456; i += 128) ws[i] = w1[i];
    for (int i = tid; i < 306; i += 128) {
        int c = i / 102;
        int r = (i % 102) / 34;
        int col = i % 34;
        int yin = y + r - 1, xin = col - 1;
        float v = 0.f;
        if (yin >= 0 && yin < 32 && xin >= 0 && xin < 32)
            v = x[((b * 3 + c) * 32 + yin) * 32 + xin];
        xs[i] = v;
    }
    __syncthreads();

    int oc = tid;
    float wsgn[27];
#pragma unroll
    for (int k = 0; k < 27; k++) {
        float wv = ws[oc * 27 + k];
        wsgn[k] = (wv > 0.f) ? 1.f : ((wv < 0.f) ? -1.f : 0.f);
    }
    float sv = s1[oc], tv = t1[oc];
    int lane = tid & 31, wid = tid >> 5;

    for (int x8 = 0; x8 < 32; x8 += 8) {
        float acc[8];
#pragma unroll
        for (int u = 0; u < 8; u++) {
            int xo = x8 + u;
            float a = 0.f;
#pragma unroll
            for (int ky = 0; ky < 3; ky++)
#pragma unroll
                for (int kx = 0; kx < 3; kx++)
#pragma unroll
                    for (int c = 0; c < 3; c++)
                        a = __fmaf_rn(xs[c * 102 + ky * 34 + xo + kx],
                                      wsgn[c * 9 + ky * 3 + kx], a);
            acc[u] = a;
        }
#pragma unroll
        for (int u = 0; u < 8; u++) {
            float v = __fadd_rn(__fmul_rn(acc[u], sv), tv);
            unsigned word = __ballot_sync(0xffffffffu, v > 0.f);
            if (lane == 0)
                g_a1[((b * 32 + y) * 32 + x8 + u) * 4 + wid] = word;
        }
    }
}

// ---------------- binary conv layers (XNOR + CSA-popcount) --------------------
// One warp = 32 output channels x one output row-chunk (XC pre-pool columns).
// Sliding 3-wide window of uint4 input words; per accumulator & row, 12 xor
// words compressed by CSA tree -> 5 popcs. Boundary taps masked to zero via
// fused (a^w)&m LOP3 (valid-tap count rv*cv*CIN excludes them).
// All-integer => bit-exact vs reference. dot = validbits - 2*mismatches.
template <int CINW, int HIN, int WIN, int POOL, int COUTG, int XC>
__global__ __launch_bounds__(256) void bconv(const uint32_t* __restrict__ in,
                                             uint32_t* __restrict__ out,
                                             const uint32_t* __restrict__ wp,
                                             const float* __restrict__ s,
                                             const float* __restrict__ t) {
    constexpr int ROWS = POOL ? 2 : 1;
    constexpr int HOUT = POOL ? HIN / 2 : HIN;
    constexpr int WOUT = POOL ? WIN / 2 : WIN;
    constexpr int CIN  = CINW * 32;
    constexpr int COUT = COUTG * 32;
    constexpr int NCH  = WIN / XC;

    int lane = threadIdx.x & 31;
    int gw = blockIdx.x * (blockDim.x >> 5) + (threadIdx.x >> 5);
    int total = NB * COUTG * HOUT * NCH;
    if (gw >= total) return;
    int xch = gw % NCH;
    int rem = gw / NCH;
    int yr  = rem % HOUT;
    int tm  = rem / HOUT;
    int ocg = tm % COUTG;
    int b   = tm / COUTG;
    int oc  = ocg * 32 + lane;
    int x0  = (NCH == 1) ? 0 : xch * XC;
    int yc0 = POOL ? yr * 2 : yr;

    int m[ROWS][XC];
#pragma unroll
    for (int r = 0; r < ROWS; r++)
#pragma unroll
        for (int xx = 0; xx < XC; xx++) m[r][xx] = 0;

#pragma unroll
    for (int cw0 = 0; cw0 < CINW; cw0 += 4) {
        uint32_t wr[9][4];
#pragma unroll
        for (int kk = 0; kk < 9; kk++) {
            uint4 q = *reinterpret_cast<const uint4*>(
                wp + ((kk * (CINW >> 2) + (cw0 >> 2)) * COUT + oc) * 4);
            wr[kk][0] = q.x; wr[kk][1] = q.y; wr[kk][2] = q.z; wr[kk][3] = q.w;
        }

#pragma unroll
        for (int yl = 0; yl < ROWS + 2; yl++) {
            int yin = yc0 + yl - 1;
            if (yin < 0 || yin >= HIN) continue;   // padded row contributes 0
            const uint32_t* rowp = in + ((b * HIN + yin) * WIN) * CINW + cw0;

            uint4 a0, a1, a2;
            uint32_t k0, k1, k2;
            if (x0 > 0) { a0 = *reinterpret_cast<const uint4*>(rowp + (x0 - 1) * CINW); k0 = ~0u; }
            else        { a0 = make_uint4(0u, 0u, 0u, 0u); k0 = 0u; }
            a1 = *reinterpret_cast<const uint4*>(rowp + x0 * CINW); k1 = ~0u;

#pragma unroll
            for (int xl = 0; xl < XC; xl++) {
                int xg = x0 + xl + 1;
                if (xg < WIN) { a2 = *reinterpret_cast<const uint4*>(rowp + xg * CINW); k2 = ~0u; }
                else          { a2 = make_uint4(0u, 0u, 0u, 0u); k2 = 0u; }

#pragma unroll
                for (int r = 0; r < ROWS; r++) {
                    int ky = yl - r;
                    if (ky < 0 || ky > 2) continue;   // compile-time after unroll
                    uint32_t p[12];
                    p[0]  = (a0.x ^ wr[ky*3+0][0]) & k0;
                    p[1]  = (a0.y ^ wr[ky*3+0][1]) & k0;
                    p[2]  = (a0.z ^ wr[ky*3+0][2]) & k0;
                    p[3]  = (a0.w ^ wr[ky*3+0][3]) & k0;
                    p[4]  = (a1.x ^ wr[ky*3+1][0]) & k1;
                    p[5]  = (a1.y ^ wr[ky*3+1][1]) & k1;
                    p[6]  = (a1.z ^ wr[ky*3+1][2]) & k1;
                    p[7]  = (a1.w ^ wr[ky*3+1][3]) & k1;
                    p[8]  = (a2.x ^ wr[ky*3+2][0]) & k2;
                    p[9]  = (a2.y ^ wr[ky*3+2][1]) & k2;
                    p[10] = (a2.z ^ wr[ky*3+2][2]) & k2;
                    p[11] = (a2.w ^ wr[ky*3+2][3]) & k2;
                    m[r][xl] += popc12(p);
                }
                a0 = a1; k0 = k1;
                a1 = a2; k1 = k2;
            }
        }
    }

    float sv = s[oc], tv = t[oc];
    if constexpr (POOL) {
#pragma unroll
        for (int xo = 0; xo < XC / 2; xo++) {
            bool p = false;
#pragma unroll
            for (int r = 0; r < ROWS; r++) {
                int yc = yc0 + r;
                int rv = 3 - (yc == 0 ? 1 : 0) - (yc == HIN - 1 ? 1 : 0);
#pragma unroll
                for (int dx = 0; dx < 2; dx++) {
                    int xcl = xo * 2 + dx;
                    int xcg = x0 + xcl;
                    int cv = 3 - (xcg == 0 ? 1 : 0) - (xcg == WIN - 1 ? 1 : 0);
                    int dot = rv * cv * CIN - 2 * m[r][xcl];
                    float v = __fadd_rn(__fmul_rn((float)dot, sv), tv);
                    p = p || (v > 0.f);   // sign(BN(maxpool)) == OR of thresholds (s>0)
                }
            }
            unsigned word = __ballot_sync(0xffffffffu, p);
            if (lane == 0)
                out[((b * HOUT + yr) * WOUT + (x0 / 2 + xo)) * COUTG + ocg] = word;
        }
    } else {
#pragma unroll
        for (int xcl = 0; xcl < XC; xcl++) {
            int xcg = x0 + xcl;
            int rv = 3 - (yc0 == 0 ? 1 : 0) - (yc0 == HIN - 1 ? 1 : 0);
            int cv = 3 - (xcg == 0 ? 1 : 0) - (xcg == WIN - 1 ? 1 : 0);
            int dot = rv * cv * CIN - 2 * m[0][xcl];
            float v = __fadd_rn(__fmul_rn((float)dot, sv), tv);
            unsigned word = __ballot_sync(0xffffffffu, v > 0.f);
            if (lane == 0)
                out[((b * HOUT + yr) * WIN + xcg) * COUTG + ocg] = word;
        }
    }
}

// ---------------- layer 7: 4x4 VALID conv (512->10) + BN + log_softmax --------
__global__ void conv7(const float* __restrict__ s, const float* __restrict__ t,
                      float* __restrict__ outp) {
    int b = blockIdx.x;
    int wid = threadIdx.x >> 5, lane = threadIdx.x & 31;  // wid = class 0..9
    __shared__ float logits[10];

    int msum = 0;
    for (int i = lane; i < 256; i += 32) {
        int kk = i >> 4, wi = i & 15;
        uint32_t wv = g_w7p[((kk * 4 + (wi >> 2)) * 10 + wid) * 4 + (wi & 3)];
        msum += __popc(g_a6[b * 256 + i] ^ wv);
    }
#pragma unroll
    for (int off = 16; off; off >>= 1)
        msum += __shfl_down_sync(0xffffffffu, msum, off);
    if (lane == 0) {
        int dot = 8192 - 2 * msum;  // 512*16 taps, all valid (no padding)
        logits[wid] = __fadd_rn(__fmul_rn((float)dot, s[wid]), t[wid]);
    }
    __syncthreads();
    if (threadIdx.x == 0) {
        float mx = logits[0];
        for (int i = 1; i < 10; i++) mx = fmaxf(mx, logits[i]);
        float ssum = 0.f;
        for (int i = 0; i < 10; i++) ssum += expf(logits[i] - mx);
        float lse = mx + logf(ssum);
        for (int i = 0; i < 10; i++) outp[b * 10 + i] = logits[i] - lse;
    }
}

// ---------------- launcher ----------------------------------------------------
extern "C" void kernel_launch(void* const* d_in, const int* in_sizes, int n_in,
                              void* d_out, int out_size) {
    const float* x  = (const float*)d_in[0];
    const float* w1 = (const float*)d_in[1];
    const float* w2 = (const float*)d_in[2];
    const float* w3 = (const float*)d_in[3];
    const float* w4 = (const float*)d_in[4];
    const float* w5 = (const float*)d_in[5];
    const float* w6 = (const float*)d_in[6];
    const float* w7 = (const float*)d_in[7];
    const float* bns[7];
    const float* bnt[7];
    for (int i = 0; i < 7; i++) {
        bns[i] = (const float*)d_in[8 + 2 * i];
        bnt[i] = (const float*)d_in[9 + 2 * i];
    }
    float* out = (float*)d_out;

    void *pa1, *pa2, *pa3, *pa4, *pa5, *pa6;
    void *pw2, *pw3, *pw4, *pw5, *pw6, *pw7;
    cudaGetSymbolAddress(&pa1, g_a1);
    cudaGetSymbolAddress(&pa2, g_a2);
    cudaGetSymbolAddress(&pa3, g_a3);
    cudaGetSymbolAddress(&pa4, g_a4);
    cudaGetSymbolAddress(&pa5, g_a5);
    cudaGetSymbolAddress(&pa6, g_a6);
    cudaGetSymbolAddress(&pw2, g_w2p);
    cudaGetSymbolAddress(&pw3, g_w3p);
    cudaGetSymbolAddress(&pw4, g_w4p);
    cudaGetSymbolAddress(&pw5, g_w5p);
    cudaGetSymbolAddress(&pw6, g_w6p);
    cudaGetSymbolAddress(&pw7, g_w7p);

    // 0: layer1, 1: merged packs
    layer1<<<NB * 32, 128>>>(x, w1, bns[0], bnt[0]);
    packAll<<<1674, 256>>>(w2, w3, w4, w5, w6, w7,
                           (uint32_t*)pw2, (uint32_t*)pw3, (uint32_t*)pw4,
                           (uint32_t*)pw5, (uint32_t*)pw6, (uint32_t*)pw7);
    // 2-6: binary conv layers. Pool layers XC=4 (8 accumulators -> ~75 regs,
    // 3 CTAs/SM) — the occupancy fix from R9 WITHOUT the Harley-Seal serial
    // chain that caused the regression. Non-pool layers keep XC=8.
    bconv<4, 32, 32, 1, 4, 4><<<8192, 256>>>(
        (uint32_t*)pa1, (uint32_t*)pa2, (uint32_t*)pw2, bns[1], bnt[1]);
    bconv<4, 16, 16, 0, 8, 8><<<4096, 256>>>(
        (uint32_t*)pa2, (uint32_t*)pa3, (uint32_t*)pw3, bns[2], bnt[2]);
    bconv<8, 16, 16, 1, 8, 4><<<4096, 256>>>(
        (uint32_t*)pa3, (uint32_t*)pa4, (uint32_t*)pw4, bns[3], bnt[3]);
    bconv<8, 8, 8, 0, 16, 8><<<2048, 256>>>(
        (uint32_t*)pa4, (uint32_t*)pa5, (uint32_t*)pw5, bns[4], bnt[4]);
    bconv<16, 8, 8, 1, 16, 4><<<2048, 256>>>(
        (uint32_t*)pa5, (uint32_t*)pa6, (uint32_t*)pw6, bns[5], bnt[5]);
    // 7: head
    conv7<<<NB, 320>>>(bns[6], bnt[6], out);
}